// round 5
// baseline (speedup 1.0000x reference)
#include <cuda_runtime.h>

#define N_ROWS   1000000
#define N_FEAT   100
#define N_BINS   256
#define GRID_B   148
#define ROWS_PER 6784            // every block's row count is a multiple of 64 (nsc = 212 or 86, even)
#define SMEM_BYTES 204800        // 2 halves * (3 warps*256*32*4 + 1 warp*256*4*4)
#define HALF_BYTES 102400

// Per-block partial histograms, scalar floats: [block][half][feature][bin].
__device__ float  g_part[GRID_B * 2 * N_FEAT * N_BINS];
// Stage-1 reduced partials: [feature][quarter][bin] as float2 (g,h).
__device__ float2 g_red[N_FEAT * 4 * N_BINS];

__global__ __launch_bounds__(256, 1)
void hist_kernel(const int* __restrict__ X,
                 const float* __restrict__ grad,
                 const float* __restrict__ hess)
{
    extern __shared__ unsigned char smem_raw[];

    const int tid  = threadIdx.x;
    const int w    = tid >> 5;
    const int lane = tid & 31;
    const int half = w >> 2;             // 0: gradient, 1: hessian
    const int w3   = w & 3;              // warp index within half
    const int f    = tid & 127;          // feature owned by this thread
    const bool act = (f < N_FEAT);
    const float* __restrict__ val = half ? hess : grad;

    // Transposed warp-private region: element (lane, b) at base + (b<<sh) + lane*4.
    // Full warps (w3<3): bank = lane -> conflict-free. Tail warp: 4 active lanes.
    const int      sh   = (w3 < 3) ? 7 : 4;
    const unsigned base = half * HALF_BYTES +
                          ((w3 < 3) ? (unsigned)(w3 * 32768) : 98304u);
    unsigned char* const histBase = smem_raw + base + lane * 4;

    // ---- zero smem ----
    {
        float4 z = make_float4(0.f, 0.f, 0.f, 0.f);
        float4* s4 = reinterpret_cast<float4*>(smem_raw);
        for (int i = tid; i < SMEM_BYTES / 16; i += 256) s4[i] = z;
    }
    __syncthreads();

    const int rowStart = blockIdx.x * ROWS_PER;
    const int rowEnd   = min(rowStart + ROWS_PER, N_ROWS);
    const int nsc      = (rowEnd - rowStart) >> 5;   // exact and even (212 or 86)

    // Per-warp cyclic superchunk start: desynchronizes the 8 data-independent
    // warps so their LDS-wait windows and LDG bursts don't coincide.
    // Even-aligned to preserve double-buffer parity.
    const int s0 = ((w * nsc) >> 3) & ~1;

    const int* xcol = X + rowStart * N_FEAT + f;

    // ---- load one 32-row superchunk (by wrapped index) ----
    auto loadSC = [&](int s, int (&bins)[32], float4 (&gv)[8]) {
        int sc = s0 + s; if (sc >= nsc) sc -= nsc;
        const int* p = xcol + sc * (32 * N_FEAT);
#pragma unroll
        for (int k = 0; k < 32; ++k)
            bins[k] = act ? __ldg(p + k * N_FEAT) : 0;
        const float4* vp = reinterpret_cast<const float4*>(val + rowStart + sc * 32);
#pragma unroll
        for (int c = 0; c < 8; ++c)
            gv[c] = __ldg(vp + c);       // warp-uniform address -> broadcast
    };

    // ---- process one superchunk: 4-row chunks, duplicate-merged, batched RMW ----
    auto processSC = [&](const int (&bins)[32], const float4 (&gv)[8]) {
#pragma unroll
        for (int c = 0; c < 8; ++c) {
            const int k = 4 * c;
            const int b0 = bins[k], b1 = bins[k + 1], b2 = bins[k + 2], b3 = bins[k + 3];
            const float g0 = gv[c].x, g1 = gv[c].y, g2 = gv[c].z, g3 = gv[c].w;

            const bool p01 = (b0 == b1), p02 = (b0 == b2), p03 = (b0 == b3);
            const bool p12 = (b1 == b2), p13 = (b1 == b3), p23 = (b2 == b3);

            float G0 = g0, G1 = g1, G2 = g2, G3 = g3;
            if (p01) G1 += g0;
            if (p02) G2 += g0;
            if (p12) G2 += g1;
            if (p03) G3 += g0;
            if (p13) G3 += g1;
            if (p23) G3 += g2;
            if (p01 | p02 | p03) G0 = 0.f;
            if (p12 | p13)       G1 = 0.f;
            if (p23)             G2 = 0.f;

            if (act) {
                float* a0 = reinterpret_cast<float*>(histBase + ((unsigned)b0 << sh));
                float* a1 = reinterpret_cast<float*>(histBase + ((unsigned)b1 << sh));
                float* a2 = reinterpret_cast<float*>(histBase + ((unsigned)b2 << sh));
                float* a3 = reinterpret_cast<float*>(histBase + ((unsigned)b3 << sh));
                float v0 = *a0, v1 = *a1, v2 = *a2, v3 = *a3;
                v0 += G0; v1 += G1; v2 += G2; v3 += G3;
                *a0 = v0; *a1 = v1; *a2 = v2; *a3 = v3;   // thread-order: last alias wins
            }
        }
    };

    // ---- double-buffered main loop over wrapped superchunk sequence ----
    int    binsA[32], binsB[32];
    float4 gvA[8],  gvB[8];
    loadSC(0, binsA, gvA);
    for (int s = 0; s < nsc; s += 2) {
        loadSC(s + 1, binsB, gvB);
        processSC(binsA, gvA);
        if (s + 2 < nsc) loadSC(s + 2, binsA, gvA);
        processSC(binsB, gvB);
    }

    __syncthreads();

    // ---- dump private histogram -> global partials (STG.128) ----
    if (act) {
        float4* myPart = reinterpret_cast<float4*>(
            g_part + ((blockIdx.x * 2 + half) * N_FEAT + f) * N_BINS);
#pragma unroll 4
        for (int b = 0; b < N_BINS; b += 4) {
            float4 v;
            v.x = *reinterpret_cast<float*>(histBase + ((unsigned)(b + 0) << sh));
            v.y = *reinterpret_cast<float*>(histBase + ((unsigned)(b + 1) << sh));
            v.z = *reinterpret_cast<float*>(histBase + ((unsigned)(b + 2) << sh));
            v.w = *reinterpret_cast<float*>(histBase + ((unsigned)(b + 3) << sh));
            myPart[b >> 2] = v;
        }
    }
}

// Stage 1: 400 blocks, block (f, q) reduces 37 of the 148 partials.
__global__ __launch_bounds__(256)
void reduce1_kernel()
{
    const int f   = blockIdx.x >> 2;
    const int q   = blockIdx.x & 3;
    const int tid = threadIdx.x;

    float gs = 0.f, hs = 0.f;
    const int blk0 = q * 37;
#pragma unroll 4
    for (int i = 0; i < 37; ++i) {
        const int blk = blk0 + i;
        gs += g_part[((blk * 2 + 0) * N_FEAT + f) * N_BINS + tid];
        hs += g_part[((blk * 2 + 1) * N_FEAT + f) * N_BINS + tid];
    }
    g_red[(f * 4 + q) * N_BINS + tid] = make_float2(gs, hs);
}

// Stage 2: 100 blocks, reduce 4 quarters + inclusive scan over 256 bins.
__global__ __launch_bounds__(256)
void reduce2_kernel(float* __restrict__ out)
{
    const int f   = blockIdx.x;
    const int tid = threadIdx.x;

    float2 acc = make_float2(0.f, 0.f);
#pragma unroll
    for (int q = 0; q < 4; ++q) {
        float2 v = g_red[(f * 4 + q) * N_BINS + tid];
        acc.x += v.x; acc.y += v.y;
    }

    __shared__ float2 buf[N_BINS];
    buf[tid] = acc;
    __syncthreads();
#pragma unroll
    for (int off = 1; off < N_BINS; off <<= 1) {
        float2 t = make_float2(0.f, 0.f);
        const bool pred = (tid >= off);
        if (pred) t = buf[tid - off];
        __syncthreads();
        if (pred) { buf[tid].x += t.x; buf[tid].y += t.y; }
        __syncthreads();
    }
    float2 r = buf[tid];
    out[f * N_BINS + tid]                   = r.x;   // Gl
    out[N_FEAT * N_BINS + f * N_BINS + tid] = r.y;   // Hl
}

extern "C" void kernel_launch(void* const* d_in, const int* in_sizes, int n_in,
                              void* d_out, int out_size)
{
    const int*   X = (const int*)d_in[0];
    const float* g = (const float*)d_in[1];
    const float* h = (const float*)d_in[2];
    float* out = (float*)d_out;

    (void)cudaFuncSetAttribute(hist_kernel,
                               cudaFuncAttributeMaxDynamicSharedMemorySize, SMEM_BYTES);

    hist_kernel<<<GRID_B, 256, SMEM_BYTES>>>(X, g, h);
    reduce1_kernel<<<N_FEAT * 4, 256>>>();
    reduce2_kernel<<<N_FEAT, 256>>>(out);
}

// round 6
// speedup vs baseline: 1.6717x; 1.6717x over previous
#include <cuda_runtime.h>

#define N_ROWS   1000000
#define N_FEAT   100
#define N_BINS   256
#define GRID_B   148
#define ROWS_PER 6784            // every block's row count is a multiple of 64 (nsc = 212 or 86, even)
#define SMEM_BYTES 204800        // 2 halves * (3 warps*256*32*4 + 1 warp*256*4*4)
#define HALF_BYTES 102400

// Per-block partial histograms, scalar floats: [block][half][feature][bin].
__device__ float  g_part[GRID_B * 2 * N_FEAT * N_BINS];
// Stage-1 reduced partials: [feature][quarter][bin] as float2 (g,h).
__device__ float2 g_red[N_FEAT * 4 * N_BINS];

__global__ __launch_bounds__(256, 1)
void hist_kernel(const int* __restrict__ X,
                 const float* __restrict__ grad,
                 const float* __restrict__ hess)
{
    extern __shared__ unsigned char smem_raw[];

    const int tid  = threadIdx.x;
    const int w    = tid >> 5;
    const int lane = tid & 31;
    const int half = w >> 2;             // 0: gradient, 1: hessian
    const int w3   = w & 3;              // warp index within half
    const int f    = tid & 127;          // feature owned by this thread
    const bool act = (f < N_FEAT);
    const float* __restrict__ val = half ? hess : grad;

    // Transposed warp-private region: element (lane, b) at base + (b<<sh) + lane*4.
    // Full warps (w3<3): bank = lane -> conflict-free. Tail warp: 4 active lanes.
    const int      sh   = (w3 < 3) ? 7 : 4;
    const unsigned base = half * HALF_BYTES +
                          ((w3 < 3) ? (unsigned)(w3 * 32768) : 98304u);
    unsigned char* const histBase = smem_raw + base + lane * 4;

    // ---- zero smem ----
    {
        float4 z = make_float4(0.f, 0.f, 0.f, 0.f);
        float4* s4 = reinterpret_cast<float4*>(smem_raw);
        for (int i = tid; i < SMEM_BYTES / 16; i += 256) s4[i] = z;
    }
    __syncthreads();

    const int rowStart = blockIdx.x * ROWS_PER;
    const int rowEnd   = min(rowStart + ROWS_PER, N_ROWS);
    const int nsc      = (rowEnd - rowStart) >> 5;   // exact and even (212 or 86)

    const int* xcol = X + rowStart * N_FEAT + f;

    // ---- load ONE 4-row chunk of superchunk sc (4 bins + 1 broadcast val vec) ----
    // Issued interleaved with RMW chunks so the per-SM L1tex wavefront queue
    // stays shallow (LDS results share that FIFO with LDG returns).
    auto loadChunk = [&](int sc, int c, int (&bins)[32], float4 (&gv)[8]) {
        const int* p = xcol + sc * (32 * N_FEAT) + (4 * c) * N_FEAT;
        const int k = 4 * c;
        bins[k]     = act ? __ldg(p)              : 0;
        bins[k + 1] = act ? __ldg(p + N_FEAT)     : 0;
        bins[k + 2] = act ? __ldg(p + 2 * N_FEAT) : 0;
        bins[k + 3] = act ? __ldg(p + 3 * N_FEAT) : 0;
        const float4* vp = reinterpret_cast<const float4*>(val + rowStart + sc * 32);
        gv[c] = __ldg(vp + c);       // warp-uniform address -> broadcast
    };

    // ---- process one 4-row chunk: duplicate-merged, batched RMW ----
    auto processChunk = [&](const int (&bins)[32], const float4 (&gv)[8], int c) {
        const int k = 4 * c;
        const int b0 = bins[k], b1 = bins[k + 1], b2 = bins[k + 2], b3 = bins[k + 3];
        const float g0 = gv[c].x, g1 = gv[c].y, g2 = gv[c].z, g3 = gv[c].w;

        const bool p01 = (b0 == b1), p02 = (b0 == b2), p03 = (b0 == b3);
        const bool p12 = (b1 == b2), p13 = (b1 == b3), p23 = (b2 == b3);

        float G0 = g0, G1 = g1, G2 = g2, G3 = g3;
        if (p01) G1 += g0;
        if (p02) G2 += g0;
        if (p12) G2 += g1;
        if (p03) G3 += g0;
        if (p13) G3 += g1;
        if (p23) G3 += g2;
        if (p01 | p02 | p03) G0 = 0.f;
        if (p12 | p13)       G1 = 0.f;
        if (p23)             G2 = 0.f;

        if (act) {
            float* a0 = reinterpret_cast<float*>(histBase + ((unsigned)b0 << sh));
            float* a1 = reinterpret_cast<float*>(histBase + ((unsigned)b1 << sh));
            float* a2 = reinterpret_cast<float*>(histBase + ((unsigned)b2 << sh));
            float* a3 = reinterpret_cast<float*>(histBase + ((unsigned)b3 << sh));
            float v0 = *a0, v1 = *a1, v2 = *a2, v3 = *a3;
            v0 += G0; v1 += G1; v2 += G2; v3 += G3;
            *a0 = v0; *a1 = v1; *a2 = v2; *a3 = v3;   // thread-order: last alias wins
        }
    };

    // ---- main loop: chunk-interleaved load/RMW, double-buffered ----
    int    binsA[32], binsB[32];
    float4 gvA[8],  gvB[8];
#pragma unroll
    for (int c = 0; c < 8; ++c) loadChunk(0, c, binsA, gvA);

    for (int s = 0; s < nsc; s += 2) {
        // pass 1: process A(s), trickle-load B(s+1)
#pragma unroll
        for (int c = 0; c < 8; ++c) {
            loadChunk(s + 1, c, binsB, gvB);
            processChunk(binsA, gvA, c);
        }
        // pass 2: process B(s+1), trickle-load A(s+2)
        if (s + 2 < nsc) {
#pragma unroll
            for (int c = 0; c < 8; ++c) {
                loadChunk(s + 2, c, binsA, gvA);
                processChunk(binsB, gvB, c);
            }
        } else {
#pragma unroll
            for (int c = 0; c < 8; ++c) processChunk(binsB, gvB, c);
        }
    }

    __syncthreads();

    // ---- dump private histogram -> global partials (STG.128) ----
    if (act) {
        float4* myPart = reinterpret_cast<float4*>(
            g_part + ((blockIdx.x * 2 + half) * N_FEAT + f) * N_BINS);
#pragma unroll 4
        for (int b = 0; b < N_BINS; b += 4) {
            float4 v;
            v.x = *reinterpret_cast<float*>(histBase + ((unsigned)(b + 0) << sh));
            v.y = *reinterpret_cast<float*>(histBase + ((unsigned)(b + 1) << sh));
            v.z = *reinterpret_cast<float*>(histBase + ((unsigned)(b + 2) << sh));
            v.w = *reinterpret_cast<float*>(histBase + ((unsigned)(b + 3) << sh));
            myPart[b >> 2] = v;
        }
    }
}

// Stage 1: 400 blocks, block (f, q) reduces 37 of the 148 partials.
__global__ __launch_bounds__(256)
void reduce1_kernel()
{
    const int f   = blockIdx.x >> 2;
    const int q   = blockIdx.x & 3;
    const int tid = threadIdx.x;

    float gs = 0.f, hs = 0.f;
    const int blk0 = q * 37;
#pragma unroll 4
    for (int i = 0; i < 37; ++i) {
        const int blk = blk0 + i;
        gs += g_part[((blk * 2 + 0) * N_FEAT + f) * N_BINS + tid];
        hs += g_part[((blk * 2 + 1) * N_FEAT + f) * N_BINS + tid];
    }
    g_red[(f * 4 + q) * N_BINS + tid] = make_float2(gs, hs);
}

// Stage 2: 100 blocks, reduce 4 quarters + inclusive scan over 256 bins.
__global__ __launch_bounds__(256)
void reduce2_kernel(float* __restrict__ out)
{
    const int f   = blockIdx.x;
    const int tid = threadIdx.x;

    float2 acc = make_float2(0.f, 0.f);
#pragma unroll
    for (int q = 0; q < 4; ++q) {
        float2 v = g_red[(f * 4 + q) * N_BINS + tid];
        acc.x += v.x; acc.y += v.y;
    }

    __shared__ float2 buf[N_BINS];
    buf[tid] = acc;
    __syncthreads();
#pragma unroll
    for (int off = 1; off < N_BINS; off <<= 1) {
        float2 t = make_float2(0.f, 0.f);
        const bool pred = (tid >= off);
        if (pred) t = buf[tid - off];
        __syncthreads();
        if (pred) { buf[tid].x += t.x; buf[tid].y += t.y; }
        __syncthreads();
    }
    float2 r = buf[tid];
    out[f * N_BINS + tid]                   = r.x;   // Gl
    out[N_FEAT * N_BINS + f * N_BINS + tid] = r.y;   // Hl
}

extern "C" void kernel_launch(void* const* d_in, const int* in_sizes, int n_in,
                              void* d_out, int out_size)
{
    const int*   X = (const int*)d_in[0];
    const float* g = (const float*)d_in[1];
    const float* h = (const float*)d_in[2];
    float* out = (float*)d_out;

    (void)cudaFuncSetAttribute(hist_kernel,
                               cudaFuncAttributeMaxDynamicSharedMemorySize, SMEM_BYTES);

    hist_kernel<<<GRID_B, 256, SMEM_BYTES>>>(X, g, h);
    reduce1_kernel<<<N_FEAT * 4, 256>>>();
    reduce2_kernel<<<N_FEAT, 256>>>(out);
}